// round 9
// baseline (speedup 1.0000x reference)
#include <cuda_runtime.h>
#include <cuda_fp16.h>
#include <cuda_bf16.h>
#include <mma.h>

using namespace nvcuda;

#define N_NODES 100000
#define E_MAX   3400000
#define F 128
#define SCAN_NBLK ((N_NODES + 1023) / 1024)   // 98

// ---- static device scratch (allocation-free requirement) ----
__device__ float  g_h0[N_NODES * F];
__device__ float  g_h1[N_NODES * F];
__device__ float  g_g [N_NODES * F];          // fp32 path (layer-4 logits)
__device__ __half g_g16[N_NODES * F];         // fp16 gather payload (layers 1-3)
__device__ float  g_dinv[N_NODES];
__device__ int    g_cnt[N_NODES];
__device__ int    g_pos[N_NODES];
__device__ int    g_rowptr[N_NODES + 1];
__device__ int    g_col[E_MAX];
__device__ int    g_bsum[128];
__device__ int    g_boff[128];

__device__ __forceinline__ float* pick(int s) { return s == 0 ? g_h0 : g_h1; }

struct alignas(16) Half8 { __half2 a, b, c, d; };
struct alignas(16) BF8   { __nv_bfloat162 a, b, c, d; };

// ---- packed f32x2 FMA helpers (gemm32) ----
__device__ __forceinline__ void ffma2(unsigned long long& d,
                                      unsigned long long a, unsigned long long b) {
    asm("fma.rn.f32x2 %0, %1, %2, %0;" : "+l"(d) : "l"(a), "l"(b));
}
__device__ __forceinline__ unsigned long long pack2(float x, float y) {
    unsigned long long r;
    asm("mov.b64 %0, {%1, %2};" : "=l"(r) : "f"(x), "f"(y));
    return r;
}
__device__ __forceinline__ void unpack2(unsigned long long v, float& x, float& y) {
    unsigned lo, hi;
    asm("mov.b64 {%0, %1}, %2;" : "=r"(lo), "=r"(hi) : "l"(v));
    x = __uint_as_float(lo); y = __uint_as_float(hi);
}

__device__ __forceinline__ BF8 to_bf8(float4 a0, float4 a1) {
    BF8 b;
    b.a = __floats2bfloat162_rn(a0.x, a0.y);
    b.b = __floats2bfloat162_rn(a0.z, a0.w);
    b.c = __floats2bfloat162_rn(a1.x, a1.y);
    b.d = __floats2bfloat162_rn(a1.z, a1.w);
    return b;
}

// ---------------- CSR construction ----------------
// edge_index is int32 (JAX default x64-disabled).

__global__ void k_zero() {
    int i = blockIdx.x * blockDim.x + threadIdx.x;
    if (i < N_NODES) { g_cnt[i] = 0; g_pos[i] = 0; }
}

__global__ void k_count(const int* __restrict__ ei, int E) {
    int e = blockIdx.x * blockDim.x + threadIdx.x;
    if (e < E) {
        int d = ei[E + e];
        if ((unsigned)d < N_NODES) atomicAdd(&g_cnt[d], 1);
    }
}

__global__ void k_dinv() {
    int i = blockIdx.x * blockDim.x + threadIdx.x;
    if (i < N_NODES) {
        float deg = (float)(g_cnt[i] + 1);   // +1 self loop
        g_dinv[i] = rsqrtf(deg);
    }
}

__global__ __launch_bounds__(1024) void k_scan1() {
    __shared__ int wsum[32];
    int tid = threadIdx.x, lane = tid & 31, wid = tid >> 5;
    int i = blockIdx.x * 1024 + tid;
    int v = (i < N_NODES) ? g_cnt[i] : 0;
    int x = v;
    #pragma unroll
    for (int off = 1; off < 32; off <<= 1) {
        int t = __shfl_up_sync(0xffffffffu, x, off);
        if (lane >= off) x += t;
    }
    if (lane == 31) wsum[wid] = x;
    __syncthreads();
    if (wid == 0) {
        int w = wsum[lane];
        #pragma unroll
        for (int off = 1; off < 32; off <<= 1) {
            int t = __shfl_up_sync(0xffffffffu, w, off);
            if (lane >= off) w += t;
        }
        wsum[lane] = w;
    }
    __syncthreads();
    int excl = x - v + (wid ? wsum[wid - 1] : 0);
    if (i < N_NODES) g_rowptr[i] = excl;
    if (tid == 0) g_bsum[blockIdx.x] = wsum[31];
}

__global__ __launch_bounds__(128) void k_scan2() {
    __shared__ int s[128];
    int tid = threadIdx.x;
    int v = (tid < SCAN_NBLK) ? g_bsum[tid] : 0;
    s[tid] = v;
    __syncthreads();
    #pragma unroll
    for (int off = 1; off < 128; off <<= 1) {
        int t = (tid >= off) ? s[tid - off] : 0;
        __syncthreads();
        s[tid] += t;
        __syncthreads();
    }
    g_boff[tid] = s[tid] - v;          // exclusive
    if (tid == 127) g_rowptr[N_NODES] = s[127];
}

__global__ __launch_bounds__(1024) void k_scan3() {
    int i = blockIdx.x * 1024 + threadIdx.x;
    if (i < N_NODES) g_rowptr[i] += g_boff[blockIdx.x];
}

__global__ void k_fill(const int* __restrict__ ei, int E) {
    int e = blockIdx.x * blockDim.x + threadIdx.x;
    if (e < E) {
        int s = ei[e];
        int d = ei[E + e];
        if ((unsigned)s < N_NODES && (unsigned)d < N_NODES) {
            int p = atomicAdd(&g_pos[d], 1);
            g_col[g_rowptr[d] + p] = s;
        }
    }
}

// ---------------- GEMM (tensor cores): g_g16 = half((A @ W) * dinv) ----------------
// bf16 WMMA m16n16k16, fp32 accumulate. W resident in smem (staged once).
// A double-buffered: prefetch k+1 into regs before MMA of k; one sync per k-step.
// Block = 128x128 tile, 8 warps (4x2), warp = 32x64.

__global__ __launch_bounds__(256) void k_gemm128(const float* __restrict__ Aext,
                                                 int srcsel,
                                                 const float* __restrict__ W, int M) {
    const float* __restrict__ A = (srcsel < 0) ? Aext : pick(srcsel);
    __shared__ __nv_bfloat16 Wsm[128][136];     // whole W, bf16, ld=136 (272B, 16B mult)
    __shared__ __nv_bfloat16 Asm[2][128][24];   // double-buffered A tile, ld=24 (48B)

    int tid  = threadIdx.x;
    int wid  = tid >> 5;
    int lane = tid & 31;
    int row0 = blockIdx.x * 128;
    int wr = wid >> 1;          // 0..3 -> rows wr*32 .. +31
    int wc = wid & 1;           // 0..1 -> cols wc*64 .. +63

    // ---- stage entire W (fp32 -> bf16), once ----
    #pragma unroll
    for (int c = tid; c < 2048; c += 256) {     // 2048 chunks of 8 elems
        int r2 = c >> 4;                        // 0..127
        int c2 = (c & 15) * 8;
        float4 b0 = *(const float4*)&W[r2 * 128 + c2];
        float4 b1 = *(const float4*)&W[r2 * 128 + c2 + 4];
        *(BF8*)&Wsm[r2][c2] = to_bf8(b0, b1);
    }

    // ---- A staging geometry: thread -> (row, 8-elem column chunk) ----
    int ar    = tid >> 1;
    int acst  = (tid & 1) * 8;
    int agrow = row0 + ar;
    bool valid = agrow < M;
    const float* Arow = &A[(long long)agrow * 128 + acst];
    float4 z4 = make_float4(0.f, 0.f, 0.f, 0.f);

    // prologue: stage k-step 0
    {
        float4 p0 = valid ? *(const float4*)&Arow[0] : z4;
        float4 p1 = valid ? *(const float4*)&Arow[4] : z4;
        *(BF8*)&Asm[0][ar][acst] = to_bf8(p0, p1);
    }
    __syncthreads();

    wmma::fragment<wmma::accumulator, 16, 16, 16, float> c[2][4];
    #pragma unroll
    for (int i = 0; i < 2; i++)
        #pragma unroll
        for (int j = 0; j < 4; j++) wmma::fill_fragment(c[i][j], 0.f);

    #pragma unroll
    for (int kk = 0; kk < 8; kk++) {
        int cur = kk & 1;
        float4 n0, n1;
        if (kk < 7) {                            // issue next tile's global loads early
            n0 = valid ? *(const float4*)&Arow[(kk + 1) * 16]     : z4;
            n1 = valid ? *(const float4*)&Arow[(kk + 1) * 16 + 4] : z4;
        }
        wmma::fragment<wmma::matrix_a, 16, 16, 16, __nv_bfloat16, wmma::row_major> af[2];
        wmma::fragment<wmma::matrix_b, 16, 16, 16, __nv_bfloat16, wmma::row_major> bf[4];
        #pragma unroll
        for (int i = 0; i < 2; i++)
            wmma::load_matrix_sync(af[i], &Asm[cur][wr * 32 + i * 16][0], 24);
        #pragma unroll
        for (int j = 0; j < 4; j++)
            wmma::load_matrix_sync(bf[j], &Wsm[kk * 16][wc * 64 + j * 16], 136);
        #pragma unroll
        for (int i = 0; i < 2; i++)
            #pragma unroll
            for (int j = 0; j < 4; j++)
                wmma::mma_sync(c[i][j], af[i], bf[j], c[i][j]);
        if (kk < 7) {
            *(BF8*)&Asm[1 - cur][ar][acst] = to_bf8(n0, n1);
            __syncthreads();
        }
    }
    __syncthreads();                             // before aliasing Asm as epilogue staging

    // epilogue: per 16x16 tile, stage to smem (aliased in Asm), scale dinv, emit fp16
    float* Cs = ((float*)&Asm[0][0][0]) + wid * 320;     // 16 rows x ld 20
    #pragma unroll
    for (int i = 0; i < 2; i++) {
        #pragma unroll
        for (int j = 0; j < 4; j++) {
            wmma::store_matrix_sync(Cs, c[i][j], 20, wmma::mem_row_major);
            __syncwarp();
            int rr = lane >> 1;              // 0..15
            int c0 = (lane & 1) * 8;         // 0 or 8
            int grow = row0 + wr * 32 + i * 16 + rr;
            if (grow < M) {
                float d = g_dinv[grow];
                const float* src = &Cs[rr * 20 + c0];
                Half8 h;
                h.a = __floats2half2_rn(src[0] * d, src[1] * d);
                h.b = __floats2half2_rn(src[2] * d, src[3] * d);
                h.c = __floats2half2_rn(src[4] * d, src[5] * d);
                h.d = __floats2half2_rn(src[6] * d, src[7] * d);
                *(Half8*)&g_g16[(long long)grow * 128 + wc * 64 + j * 16 + c0] = h;
            }
            __syncwarp();
        }
    }
}

// ---------------- GEMM 128x32 (last layer), fp32 FFMA2 -> g_g as [M,32] ----------

__global__ __launch_bounds__(256) void k_gemm32(int srcsel,
                                                const float* __restrict__ W, int M) {
    const float* __restrict__ A = pick(srcsel);
    __shared__ float As[16][128];
    __shared__ float Bs[16][32];
    int tid = threadIdx.x;
    int row0 = blockIdx.x * 128;
    int tr = tid >> 3;     // 0..31
    int tc = tid & 7;      // 0..7
    unsigned long long acc[2][4];
    #pragma unroll
    for (int p = 0; p < 2; p++)
        #pragma unroll
        for (int j = 0; j < 4; j++) acc[p][j] = 0ull;

    for (int k0 = 0; k0 < 128; k0 += 16) {
        #pragma unroll
        for (int it = 0; it < 2; it++) {
            int idx = tid + it * 256;
            int r  = idx >> 2;
            int kc = (idx & 3) * 4;
            int grow = row0 + r;
            float4 a = (grow < M) ? *(const float4*)&A[(long long)grow * 128 + k0 + kc]
                                  : make_float4(0.f, 0.f, 0.f, 0.f);
            As[kc + 0][r] = a.x; As[kc + 1][r] = a.y;
            As[kc + 2][r] = a.z; As[kc + 3][r] = a.w;
        }
        if (tid < 128) {
            int r = tid >> 3;
            int c = (tid & 7) * 4;
            *(float4*)&Bs[r][c] = *(const float4*)&W[(k0 + r) * 32 + c];
        }
        __syncthreads();
        #pragma unroll
        for (int k = 0; k < 16; k++) {
            const unsigned long long* ap =
                (const unsigned long long*)&As[k][tr * 4];
            unsigned long long a01 = ap[0], a23 = ap[1];
            float b0[4];
            *(float4*)&b0[0] = *(const float4*)&Bs[k][tc * 4];
            #pragma unroll
            for (int j = 0; j < 4; j++) {
                unsigned long long bb = pack2(b0[j], b0[j]);
                ffma2(acc[0][j], a01, bb);
                ffma2(acc[1][j], a23, bb);
            }
        }
        __syncthreads();
    }
    #pragma unroll
    for (int p = 0; p < 2; p++) {
        float lo[4], hi[4];
        #pragma unroll
        for (int j = 0; j < 4; j++) unpack2(acc[p][j], lo[j], hi[j]);
        int r0 = row0 + tr * 4 + 2 * p;
        if (r0 < M) {
            float d = g_dinv[r0];
            float4 o = make_float4(lo[0] * d, lo[1] * d, lo[2] * d, lo[3] * d);
            *(float4*)&g_g[(long long)r0 * 32 + tc * 4] = o;
        }
        if (r0 + 1 < M) {
            float d = g_dinv[r0 + 1];
            float4 o = make_float4(hi[0] * d, hi[1] * d, hi[2] * d, hi[3] * d);
            *(float4*)&g_g[(long long)(r0 + 1) * 32 + tc * 4] = o;
        }
    }
}

// ---------------- Aggregation (128-wide, fp16 payload, fp32 accumulate) ----------
// warp per node; indices staged in smem; LDGs batched x8 for MLP.

__global__ __launch_bounds__(256) void k_agg128(const float* __restrict__ bias,
                                                int dstsel) {
    __shared__ int sidx[8][32];
    float* __restrict__ out = pick(dstsel);
    int wid = threadIdx.x >> 5, lane = threadIdx.x & 31;
    int gw = blockIdx.x * 8 + wid;
    if (gw >= N_NODES) return;
    const uint2* __restrict__ gg = (const uint2*)g_g16;

    uint2 self = gg[(long long)gw * 32 + lane];
    float2 f0 = __half22float2(*(__half2*)&self.x);
    float2 f1 = __half22float2(*(__half2*)&self.y);
    float4 acc = make_float4(f0.x, f0.y, f1.x, f1.y);

    int s0 = g_rowptr[gw], s1 = g_rowptr[gw + 1];
    for (int base = s0; base < s1; base += 32) {
        int n = min(32, s1 - base);
        sidx[wid][lane] = (base + lane < s1) ? g_col[base + lane] : 0;
        __syncwarp();
        int j = 0;
        for (; j + 8 <= n; j += 8) {
            uint2 v[8];
            #pragma unroll
            for (int t = 0; t < 8; t++) {
                int s = sidx[wid][j + t];
                v[t] = __ldg(&gg[(long long)s * 32 + lane]);
            }
            #pragma unroll
            for (int t = 0; t < 8; t++) {
                float2 a = __half22float2(*(__half2*)&v[t].x);
                float2 b = __half22float2(*(__half2*)&v[t].y);
                acc.x += a.x; acc.y += a.y; acc.z += b.x; acc.w += b.y;
            }
        }
        for (; j < n; j++) {
            int s = sidx[wid][j];
            uint2 v = __ldg(&gg[(long long)s * 32 + lane]);
            float2 a = __half22float2(*(__half2*)&v.x);
            float2 b = __half22float2(*(__half2*)&v.y);
            acc.x += a.x; acc.y += a.y; acc.z += b.x; acc.w += b.y;
        }
        __syncwarp();
    }
    float d = g_dinv[gw];
    float4 b = ((const float4*)bias)[lane];
    float4 o;
    o.x = fmaxf(d * acc.x + b.x, 0.f);
    o.y = fmaxf(d * acc.y + b.y, 0.f);
    o.z = fmaxf(d * acc.z + b.z, 0.f);
    o.w = fmaxf(d * acc.w + b.w, 0.f);
    ((float4*)out)[(long long)gw * 32 + lane] = o;
}

// ---------------- Aggregation (32-wide, fp32) + log_softmax fused ----------------

__global__ __launch_bounds__(256) void k_agg32_lsm(const float* __restrict__ bias,
                                                   float* __restrict__ out) {
    __shared__ int sidx[8][32];
    int wid = threadIdx.x >> 5, lane = threadIdx.x & 31;
    int gw = blockIdx.x * 8 + wid;
    if (gw >= N_NODES) return;
    float acc = g_g[(long long)gw * 32 + lane];
    int s0 = g_rowptr[gw], s1 = g_rowptr[gw + 1];
    for (int base = s0; base < s1; base += 32) {
        int n = min(32, s1 - base);
        sidx[wid][lane] = (base + lane < s1) ? g_col[base + lane] : 0;
        __syncwarp();
        int j = 0;
        for (; j + 8 <= n; j += 8) {
            float v[8];
            #pragma unroll
            for (int t = 0; t < 8; t++) {
                int s = sidx[wid][j + t];
                v[t] = __ldg(&g_g[(long long)s * 32 + lane]);
            }
            #pragma unroll
            for (int t = 0; t < 8; t++) acc += v[t];
        }
        for (; j < n; j++) {
            int s = sidx[wid][j];
            acc += __ldg(&g_g[(long long)s * 32 + lane]);
        }
        __syncwarp();
    }
    float v = g_dinv[gw] * acc + bias[lane];
    float mx = v;
    #pragma unroll
    for (int off = 16; off; off >>= 1)
        mx = fmaxf(mx, __shfl_xor_sync(0xffffffffu, mx, off));
    float e = expf(v - mx);
    float sum = e;
    #pragma unroll
    for (int off = 16; off; off >>= 1)
        sum += __shfl_xor_sync(0xffffffffu, sum, off);
    out[(long long)gw * 32 + lane] = v - mx - logf(sum);
}

// ---------------- launch ----------------

extern "C" void kernel_launch(void* const* d_in, const int* in_sizes, int n_in,
                              void* d_out, int out_size) {
    const float* x  = (const float*)d_in[0];
    const int*   ei = (const int*)d_in[1];       // int32
    const float* W1 = (const float*)d_in[2]; const float* b1 = (const float*)d_in[3];
    const float* W2 = (const float*)d_in[4]; const float* b2 = (const float*)d_in[5];
    const float* W3 = (const float*)d_in[6]; const float* b3 = (const float*)d_in[7];
    const float* W4 = (const float*)d_in[8]; const float* b4 = (const float*)d_in[9];
    float* out = (float*)d_out;
    int E = in_sizes[1] / 2;
    if (E > E_MAX) E = E_MAX;

    const int TB = 256;
    int gN = (N_NODES + TB - 1) / TB;
    int gE = (E + TB - 1) / TB;
    int gGemm = (N_NODES + 127) / 128;
    int gAgg  = (N_NODES + 7) / 8;

    // CSR build + layer-1 GEMM, ordered so k_gemm128 lands in the ncu capture slot
    k_zero   <<<gN, TB>>>();
    k_count  <<<gE, TB>>>(ei, E);
    k_dinv   <<<gN, TB>>>();
    k_gemm128<<<gGemm, TB>>>(x, -1, W1, N_NODES);   // 4th launch -> profiled
    k_scan1  <<<SCAN_NBLK, 1024>>>();
    k_scan2  <<<1, 128>>>();
    k_scan3  <<<SCAN_NBLK, 1024>>>();
    k_fill   <<<gE, TB>>>(ei, E);

    // layer 1 aggregation
    k_agg128 <<<gAgg, TB>>>(b1, 0);
    // layer 2
    k_gemm128<<<gGemm, TB>>>(nullptr, 0, W2, N_NODES);
    k_agg128 <<<gAgg, TB>>>(b2, 1);
    // layer 3
    k_gemm128<<<gGemm, TB>>>(nullptr, 1, W3, N_NODES);
    k_agg128 <<<gAgg, TB>>>(b3, 0);
    // layer 4 (transform first -> 32-wide aggregation, fp32) + log_softmax
    k_gemm32 <<<gGemm, TB>>>(0, W4, N_NODES);
    k_agg32_lsm<<<gAgg, TB>>>(b4, out);
}

// round 10
// speedup vs baseline: 1.0568x; 1.0568x over previous
#include <cuda_runtime.h>
#include <cuda_fp16.h>
#include <mma.h>

using namespace nvcuda;

#define N_NODES 100000
#define E_MAX   3400000
#define F 128
#define SCAN_NBLK ((N_NODES + 1023) / 1024)   // 98

// ---- static device scratch (allocation-free requirement) ----
__device__ __half g_h0[N_NODES * F];          // hidden states, fp16
__device__ __half g_h1[N_NODES * F];
__device__ float  g_g [N_NODES * F];          // fp32 path (layer-4 logits)
__device__ __half g_g16[N_NODES * F];         // fp16 gather payload (layers 1-3)
__device__ float  g_dinv[N_NODES];
__device__ int    g_cnt[N_NODES];
__device__ int    g_pos[N_NODES];
__device__ int    g_rowptr[N_NODES + 1];
__device__ int    g_col[E_MAX];
__device__ int    g_bsum[128];
__device__ int    g_boff[128];

__device__ __forceinline__ __half* pick(int s) { return s == 0 ? g_h0 : g_h1; }

struct alignas(16) Half8 { __half2 a, b, c, d; };

// ---- packed f32x2 FMA helpers (gemm32) ----
__device__ __forceinline__ void ffma2(unsigned long long& d,
                                      unsigned long long a, unsigned long long b) {
    asm("fma.rn.f32x2 %0, %1, %2, %0;" : "+l"(d) : "l"(a), "l"(b));
}
__device__ __forceinline__ unsigned long long pack2(float x, float y) {
    unsigned long long r;
    asm("mov.b64 %0, {%1, %2};" : "=l"(r) : "f"(x), "f"(y));
    return r;
}
__device__ __forceinline__ void unpack2(unsigned long long v, float& x, float& y) {
    unsigned lo, hi;
    asm("mov.b64 {%0, %1}, %2;" : "=r"(lo), "=r"(hi) : "l"(v));
    x = __uint_as_float(lo); y = __uint_as_float(hi);
}

__device__ __forceinline__ Half8 to_h8(float4 a0, float4 a1) {
    Half8 h;
    h.a = __floats2half2_rn(a0.x, a0.y);
    h.b = __floats2half2_rn(a0.z, a0.w);
    h.c = __floats2half2_rn(a1.x, a1.y);
    h.d = __floats2half2_rn(a1.z, a1.w);
    return h;
}

// ---------------- CSR construction ----------------
// edge_index is int32 (JAX default x64-disabled).

__global__ void k_zero() {
    int i = blockIdx.x * blockDim.x + threadIdx.x;
    if (i < N_NODES) { g_cnt[i] = 0; g_pos[i] = 0; }
}

__global__ void k_count(const int* __restrict__ ei, int E) {
    int e = blockIdx.x * blockDim.x + threadIdx.x;
    if (e < E) {
        int d = ei[E + e];
        if ((unsigned)d < N_NODES) atomicAdd(&g_cnt[d], 1);
    }
}

__global__ void k_dinv() {
    int i = blockIdx.x * blockDim.x + threadIdx.x;
    if (i < N_NODES) {
        float deg = (float)(g_cnt[i] + 1);   // +1 self loop
        g_dinv[i] = rsqrtf(deg);
    }
}

__global__ __launch_bounds__(1024) void k_scan1() {
    __shared__ int wsum[32];
    int tid = threadIdx.x, lane = tid & 31, wid = tid >> 5;
    int i = blockIdx.x * 1024 + tid;
    int v = (i < N_NODES) ? g_cnt[i] : 0;
    int x = v;
    #pragma unroll
    for (int off = 1; off < 32; off <<= 1) {
        int t = __shfl_up_sync(0xffffffffu, x, off);
        if (lane >= off) x += t;
    }
    if (lane == 31) wsum[wid] = x;
    __syncthreads();
    if (wid == 0) {
        int w = wsum[lane];
        #pragma unroll
        for (int off = 1; off < 32; off <<= 1) {
            int t = __shfl_up_sync(0xffffffffu, w, off);
            if (lane >= off) w += t;
        }
        wsum[lane] = w;
    }
    __syncthreads();
    int excl = x - v + (wid ? wsum[wid - 1] : 0);
    if (i < N_NODES) g_rowptr[i] = excl;
    if (tid == 0) g_bsum[blockIdx.x] = wsum[31];
}

__global__ __launch_bounds__(128) void k_scan2() {
    __shared__ int s[128];
    int tid = threadIdx.x;
    int v = (tid < SCAN_NBLK) ? g_bsum[tid] : 0;
    s[tid] = v;
    __syncthreads();
    #pragma unroll
    for (int off = 1; off < 128; off <<= 1) {
        int t = (tid >= off) ? s[tid - off] : 0;
        __syncthreads();
        s[tid] += t;
        __syncthreads();
    }
    g_boff[tid] = s[tid] - v;          // exclusive
    if (tid == 127) g_rowptr[N_NODES] = s[127];
}

__global__ __launch_bounds__(1024) void k_scan3() {
    int i = blockIdx.x * 1024 + threadIdx.x;
    if (i < N_NODES) g_rowptr[i] += g_boff[blockIdx.x];
}

__global__ void k_fill(const int* __restrict__ ei, int E) {
    int e = blockIdx.x * blockDim.x + threadIdx.x;
    if (e < E) {
        int s = ei[e];
        int d = ei[E + e];
        if ((unsigned)s < N_NODES && (unsigned)d < N_NODES) {
            int p = atomicAdd(&g_pos[d], 1);
            g_col[g_rowptr[d] + p] = s;
        }
    }
}

// ---------------- GEMM (tensor cores): g_g16 = half((A @ W) * dinv) ----------------
// __half WMMA m16n16k16, fp32 accumulate. R8 structure (21 KB smem, 2 blk/SM).
// Layers 2-3: A already fp16 -> raw 16B staging copies, no conversion.

__global__ __launch_bounds__(256) void k_gemm128(const float* __restrict__ Aext,
                                                 int srcsel,
                                                 const float* __restrict__ W, int M) {
    const __half* __restrict__ Ah = (srcsel < 0) ? nullptr : pick(srcsel);
    __shared__ __half As[128][24];    // ld = 24 elems (48B)
    __shared__ __half Bs[16][136];    // ld = 136 elems (272B)
    __shared__ float  Cs[8][16 * 20]; // epilogue staging, ld = 20 floats

    int tid  = threadIdx.x;
    int wid  = tid >> 5;
    int lane = tid & 31;
    int row0 = blockIdx.x * 128;
    int wr = wid >> 1;          // 0..3 -> rows wr*32 .. +31
    int wc = wid & 1;           // 0..1 -> cols wc*64 .. +63

    wmma::fragment<wmma::accumulator, 16, 16, 16, float> c[2][4];
    #pragma unroll
    for (int i = 0; i < 2; i++)
        #pragma unroll
        for (int j = 0; j < 4; j++) wmma::fill_fragment(c[i][j], 0.f);

    int ar   = tid >> 1;              // A staging row 0..127
    int acst = (tid & 1) * 8;         // 8-elem chunk, 0 or 8
    int agrow = row0 + ar;
    bool avalid = agrow < M;

    for (int k0 = 0; k0 < 128; k0 += 16) {
        // stage A: 128 rows x 16 k
        {
            Half8 h;
            if (srcsel < 0) {
                float4 a0, a1;
                if (avalid) {
                    a0 = *(const float4*)&Aext[(long long)agrow * 128 + k0 + acst];
                    a1 = *(const float4*)&Aext[(long long)agrow * 128 + k0 + acst + 4];
                } else {
                    a0 = make_float4(0.f, 0.f, 0.f, 0.f); a1 = a0;
                }
                h = to_h8(a0, a1);
            } else {
                if (avalid)
                    h = *(const Half8*)&Ah[(long long)agrow * 128 + k0 + acst];
                else
                    h.a = h.b = h.c = h.d = __half2half2(__float2half(0.f));
            }
            *(Half8*)&As[ar][acst] = h;
        }
        // stage B: 16 k x 128 cols (fp32 W -> half)
        {
            int r2 = tid >> 4;
            int c2 = (tid & 15) * 8;
            float4 b0 = *(const float4*)&W[(k0 + r2) * 128 + c2];
            float4 b1 = *(const float4*)&W[(k0 + r2) * 128 + c2 + 4];
            *(Half8*)&Bs[r2][c2] = to_h8(b0, b1);
        }
        __syncthreads();

        wmma::fragment<wmma::matrix_a, 16, 16, 16, __half, wmma::row_major> af[2];
        wmma::fragment<wmma::matrix_b, 16, 16, 16, __half, wmma::row_major> bf[4];
        #pragma unroll
        for (int i = 0; i < 2; i++)
            wmma::load_matrix_sync(af[i], &As[wr * 32 + i * 16][0], 24);
        #pragma unroll
        for (int j = 0; j < 4; j++)
            wmma::load_matrix_sync(bf[j], &Bs[0][wc * 64 + j * 16], 136);
        #pragma unroll
        for (int i = 0; i < 2; i++)
            #pragma unroll
            for (int j = 0; j < 4; j++)
                wmma::mma_sync(c[i][j], af[i], bf[j], c[i][j]);
        __syncthreads();
    }

    // epilogue: per 16x16 tile, stage to smem, scale by dinv[row], emit fp16
    #pragma unroll
    for (int i = 0; i < 2; i++) {
        #pragma unroll
        for (int j = 0; j < 4; j++) {
            wmma::store_matrix_sync(&Cs[wid][0], c[i][j], 20, wmma::mem_row_major);
            __syncwarp();
            int rr = lane >> 1;              // 0..15
            int c0 = (lane & 1) * 8;         // 0 or 8
            int grow = row0 + wr * 32 + i * 16 + rr;
            if (grow < M) {
                float d = g_dinv[grow];
                const float* src = &Cs[wid][rr * 20 + c0];
                Half8 h;
                h.a = __floats2half2_rn(src[0] * d, src[1] * d);
                h.b = __floats2half2_rn(src[2] * d, src[3] * d);
                h.c = __floats2half2_rn(src[4] * d, src[5] * d);
                h.d = __floats2half2_rn(src[6] * d, src[7] * d);
                *(Half8*)&g_g16[(long long)grow * 128 + wc * 64 + j * 16 + c0] = h;
            }
            __syncwarp();
        }
    }
}

// ---------------- GEMM 128x32 (last layer), fp16 A -> fp32 FFMA2 -> g_g [M,32] ----

__global__ __launch_bounds__(256) void k_gemm32(int srcsel,
                                                const float* __restrict__ W, int M) {
    const __half* __restrict__ A = pick(srcsel);
    __shared__ float As[16][128];
    __shared__ float Bs[16][32];
    int tid = threadIdx.x;
    int row0 = blockIdx.x * 128;
    int tr = tid >> 3;     // 0..31
    int tc = tid & 7;      // 0..7
    unsigned long long acc[2][4];
    #pragma unroll
    for (int p = 0; p < 2; p++)
        #pragma unroll
        for (int j = 0; j < 4; j++) acc[p][j] = 0ull;

    for (int k0 = 0; k0 < 128; k0 += 16) {
        #pragma unroll
        for (int it = 0; it < 2; it++) {
            int idx = tid + it * 256;
            int r  = idx >> 2;
            int kc = (idx & 3) * 4;
            int grow = row0 + r;
            float4 a;
            if (grow < M) {
                uint2 hv = *(const uint2*)&A[(long long)grow * 128 + k0 + kc];
                float2 p0 = __half22float2(*(__half2*)&hv.x);
                float2 p1 = __half22float2(*(__half2*)&hv.y);
                a = make_float4(p0.x, p0.y, p1.x, p1.y);
            } else {
                a = make_float4(0.f, 0.f, 0.f, 0.f);
            }
            As[kc + 0][r] = a.x; As[kc + 1][r] = a.y;
            As[kc + 2][r] = a.z; As[kc + 3][r] = a.w;
        }
        if (tid < 128) {
            int r = tid >> 3;
            int c = (tid & 7) * 4;
            *(float4*)&Bs[r][c] = *(const float4*)&W[(k0 + r) * 32 + c];
        }
        __syncthreads();
        #pragma unroll
        for (int k = 0; k < 16; k++) {
            const unsigned long long* ap =
                (const unsigned long long*)&As[k][tr * 4];
            unsigned long long a01 = ap[0], a23 = ap[1];
            float b0[4];
            *(float4*)&b0[0] = *(const float4*)&Bs[k][tc * 4];
            #pragma unroll
            for (int j = 0; j < 4; j++) {
                unsigned long long bb = pack2(b0[j], b0[j]);
                ffma2(acc[0][j], a01, bb);
                ffma2(acc[1][j], a23, bb);
            }
        }
        __syncthreads();
    }
    #pragma unroll
    for (int p = 0; p < 2; p++) {
        float lo[4], hi[4];
        #pragma unroll
        for (int j = 0; j < 4; j++) unpack2(acc[p][j], lo[j], hi[j]);
        int r0 = row0 + tr * 4 + 2 * p;
        if (r0 < M) {
            float d = g_dinv[r0];
            float4 o = make_float4(lo[0] * d, lo[1] * d, lo[2] * d, lo[3] * d);
            *(float4*)&g_g[(long long)r0 * 32 + tc * 4] = o;
        }
        if (r0 + 1 < M) {
            float d = g_dinv[r0 + 1];
            float4 o = make_float4(hi[0] * d, hi[1] * d, hi[2] * d, hi[3] * d);
            *(float4*)&g_g[(long long)(r0 + 1) * 32 + tc * 4] = o;
        }
    }
}

// ---------------- Aggregation (128-wide, fp16 payload, fp32 accumulate) ----------
// warp per node; indices staged in smem; LDGs batched x8 for MLP. fp16 output.

__global__ __launch_bounds__(256) void k_agg128(const float* __restrict__ bias,
                                                int dstsel) {
    __shared__ int sidx[8][32];
    __half* __restrict__ out = pick(dstsel);
    int wid = threadIdx.x >> 5, lane = threadIdx.x & 31;
    int gw = blockIdx.x * 8 + wid;
    if (gw >= N_NODES) return;
    const uint2* __restrict__ gg = (const uint2*)g_g16;

    uint2 self = gg[(long long)gw * 32 + lane];
    float2 f0 = __half22float2(*(__half2*)&self.x);
    float2 f1 = __half22float2(*(__half2*)&self.y);
    float4 acc = make_float4(f0.x, f0.y, f1.x, f1.y);

    int s0 = g_rowptr[gw], s1 = g_rowptr[gw + 1];
    for (int base = s0; base < s1; base += 32) {
        int n = min(32, s1 - base);
        sidx[wid][lane] = (base + lane < s1) ? g_col[base + lane] : 0;
        __syncwarp();
        int j = 0;
        for (; j + 8 <= n; j += 8) {
            uint2 v[8];
            #pragma unroll
            for (int t = 0; t < 8; t++) {
                int s = sidx[wid][j + t];
                v[t] = __ldg(&gg[(long long)s * 32 + lane]);
            }
            #pragma unroll
            for (int t = 0; t < 8; t++) {
                float2 a = __half22float2(*(__half2*)&v[t].x);
                float2 b = __half22float2(*(__half2*)&v[t].y);
                acc.x += a.x; acc.y += a.y; acc.z += b.x; acc.w += b.y;
            }
        }
        for (; j < n; j++) {
            int s = sidx[wid][j];
            uint2 v = __ldg(&gg[(long long)s * 32 + lane]);
            float2 a = __half22float2(*(__half2*)&v.x);
            float2 b = __half22float2(*(__half2*)&v.y);
            acc.x += a.x; acc.y += a.y; acc.z += b.x; acc.w += b.y;
        }
        __syncwarp();
    }
    float d = g_dinv[gw];
    float4 b = ((const float4*)bias)[lane];
    float rx = fmaxf(d * acc.x + b.x, 0.f);
    float ry = fmaxf(d * acc.y + b.y, 0.f);
    float rz = fmaxf(d * acc.z + b.z, 0.f);
    float rw = fmaxf(d * acc.w + b.w, 0.f);
    uint2 o;
    *(__half2*)&o.x = __floats2half2_rn(rx, ry);
    *(__half2*)&o.y = __floats2half2_rn(rz, rw);
    ((uint2*)out)[(long long)gw * 32 + lane] = o;
}

// ---------------- Aggregation (32-wide, fp32) + log_softmax fused ----------------

__global__ __launch_bounds__(256) void k_agg32_lsm(const float* __restrict__ bias,
                                                   float* __restrict__ out) {
    __shared__ int sidx[8][32];
    int wid = threadIdx.x >> 5, lane = threadIdx.x & 31;
    int gw = blockIdx.x * 8 + wid;
    if (gw >= N_NODES) return;
    float acc = g_g[(long long)gw * 32 + lane];
    int s0 = g_rowptr[gw], s1 = g_rowptr[gw + 1];
    for (int base = s0; base < s1; base += 32) {
        int n = min(32, s1 - base);
        sidx[wid][lane] = (base + lane < s1) ? g_col[base + lane] : 0;
        __syncwarp();
        int j = 0;
        for (; j + 8 <= n; j += 8) {
            float v[8];
            #pragma unroll
            for (int t = 0; t < 8; t++) {
                int s = sidx[wid][j + t];
                v[t] = __ldg(&g_g[(long long)s * 32 + lane]);
            }
            #pragma unroll
            for (int t = 0; t < 8; t++) acc += v[t];
        }
        for (; j < n; j++) {
            int s = sidx[wid][j];
            acc += __ldg(&g_g[(long long)s * 32 + lane]);
        }
        __syncwarp();
    }
    float v = g_dinv[gw] * acc + bias[lane];
    float mx = v;
    #pragma unroll
    for (int off = 16; off; off >>= 1)
        mx = fmaxf(mx, __shfl_xor_sync(0xffffffffu, mx, off));
    float e = expf(v - mx);
    float sum = e;
    #pragma unroll
    for (int off = 16; off; off >>= 1)
        sum += __shfl_xor_sync(0xffffffffu, sum, off);
    out[(long long)gw * 32 + lane] = v - mx - logf(sum);
}

// ---------------- launch ----------------

extern "C" void kernel_launch(void* const* d_in, const int* in_sizes, int n_in,
                              void* d_out, int out_size) {
    const float* x  = (const float*)d_in[0];
    const int*   ei = (const int*)d_in[1];       // int32
    const float* W1 = (const float*)d_in[2]; const float* b1 = (const float*)d_in[3];
    const float* W2 = (const float*)d_in[4]; const float* b2 = (const float*)d_in[5];
    const float* W3 = (const float*)d_in[6]; const float* b3 = (const float*)d_in[7];
    const float* W4 = (const float*)d_in[8]; const float* b4 = (const float*)d_in[9];
    float* out = (float*)d_out;
    int E = in_sizes[1] / 2;
    if (E > E_MAX) E = E_MAX;

    const int TB = 256;
    int gN = (N_NODES + TB - 1) / TB;
    int gE = (E + TB - 1) / TB;
    int gGemm = (N_NODES + 127) / 128;
    int gAgg  = (N_NODES + 7) / 8;

    // CSR build + layer-1 GEMM, ordered so k_gemm128 lands in the ncu capture slot
    k_zero   <<<gN, TB>>>();
    k_count  <<<gE, TB>>>(ei, E);
    k_dinv   <<<gN, TB>>>();
    k_gemm128<<<gGemm, TB>>>(x, -1, W1, N_NODES);   // 4th launch -> profiled
    k_scan1  <<<SCAN_NBLK, 1024>>>();
    k_scan2  <<<1, 128>>>();
    k_scan3  <<<SCAN_NBLK, 1024>>>();
    k_fill   <<<gE, TB>>>(ei, E);

    // layer 1 aggregation
    k_agg128 <<<gAgg, TB>>>(b1, 0);
    // layer 2
    k_gemm128<<<gGemm, TB>>>(nullptr, 0, W2, N_NODES);
    k_agg128 <<<gAgg, TB>>>(b2, 1);
    // layer 3
    k_gemm128<<<gGemm, TB>>>(nullptr, 1, W3, N_NODES);
    k_agg128 <<<gAgg, TB>>>(b3, 0);
    // layer 4 (transform first -> 32-wide aggregation, fp32) + log_softmax
    k_gemm32 <<<gGemm, TB>>>(0, W4, N_NODES);
    k_agg32_lsm<<<gAgg, TB>>>(b4, out);
}